// round 8
// baseline (speedup 1.0000x reference)
#include <cuda_runtime.h>
#include <cuda_bf16.h>
#include <math.h>
#include <stdint.h>

#define BB 1024
#define DD 64
#define HH 128
#define IB 2            // i's per CTA
#define MT 128          // j's per tile
#define THREADS 256

#if defined(__CUDA_ARCH_FEAT_SM103_ALL) || defined(__CUDA_ARCH_FEAT_SM100_ALL) || \
    defined(__CUDA_ARCH_FEAT_SM101_ALL)
#define HAS_TCGEN05 1
#else
#define HAS_TCGEN05 0
#endif

// pair kernel dynamic smem layout (bytes)
#define OFF_A     0          // Wab^T bf16 [128h x 64k] SW128, 16384
#define OFF_A2    16384      // (Wj-Wd)^T bf16 [128h x 64k] SW128, 16384
#define OFF_B     32768      // 2 x |delta| bf16 [128j x 64k] SW128, 32768
#define OFF_BX    65536      // bf16 x_j [128j x 64k] SW128, 16384
#define OFF_XI    81920      // x_i f32 [2 x 64], 512
#define OFF_SC    82432      // S partials f32 [2][2][128], 2048
#define OFF_MBAR  84480
#define OFF_TPTR  84488
#define SMEM_TOTAL 84512

// precompute kernel smem
#define OFF_W     0          // W1 rows 0..191 f32 [192 x 128], 98304
#define OFF_PXI   98304      // x_i f32 [2 x 64], 512
#define PRE_SMEM  98816

// idesc: dtype=F32, a=BF16, b=BF16, N=128, M=128 (same as proven R7)
#define IDESC ((1u << 4) | (1u << 7) | (1u << 10) | ((HH / 8) << 17) | ((MT / 16) << 24))

// Scratch
__device__ __align__(16) float g_T1[BB * HH];
__device__ __align__(16) float g_T2[BB * HH];      // fallback path only
__device__ __align__(16) float g_Sp[2][BB * HH];   // per-jh-half S partials
__device__ float g_tau[BB];

__device__ __forceinline__ uint32_t pack_bf2(float lo, float hi) {
  __nv_bfloat162 v = __floats2bfloat162_rn(lo, hi);
  return *(uint32_t*)&v;
}
__device__ __forceinline__ uint32_t sw128(uint32_t o) {
  return o ^ ((o >> 3) & 0x70);
}
__device__ __forceinline__ uint64_t smem_desc(uint32_t addr) {
  // SW128, version=1 (Blackwell), SBO=64, LBO=1
  return (2ull << 61) | (1ull << 46) | (64ull << 32) | (1ull << 16) |
         ((uint64_t)(addr >> 4) & 0x3FFF);
}
__device__ __forceinline__ void cp16(uint32_t smem_dst, const void* gsrc) {
  asm volatile("cp.async.cg.shared.global [%0], [%1], 16;" ::"r"(smem_dst),
               "l"(gsrc)
               : "memory");
}

#if HAS_TCGEN05
__device__ __forceinline__ void mma_f16_ss(uint32_t d, uint64_t ad, uint64_t bd,
                                           uint32_t idesc, bool accum) {
  uint32_t en = accum ? 1u : 0u;
  asm volatile(
      "{\n\t.reg .pred p;\n\tsetp.ne.u32 p, %5, 0;\n\t"
      "tcgen05.mma.cta_group::1.kind::f16 [%0], %1, %2, %3, {%4,%4,%4,%4}, "
      "p;\n\t}"
      :: "r"(d), "l"(ad), "l"(bd), "r"(idesc), "r"(0u), "r"(en)
      : "memory");
}
__device__ __forceinline__ void mbar_wait(uint32_t mbar, int parity) {
  asm volatile(
      "{\n\t.reg .pred P;\n\t"
      "WL%=:\n\t"
      "mbarrier.try_wait.parity.acquire.cta.shared::cta.b64 P, [%0], %1, "
      "0x989680;\n\t"
      "@P bra WD%=;\n\t"
      "bra WL%=;\n\t"
      "WD%=:\n\t}"
      :: "r"(mbar), "r"((uint32_t)parity)
      : "memory");
}
#define LDTM_X16(r, a)                                                       \
  asm volatile(                                                              \
      "tcgen05.ld.sync.aligned.32x32b.x16.b32 "                              \
      "{%0,%1,%2,%3,%4,%5,%6,%7,%8,%9,%10,%11,%12,%13,%14,%15}, [%16];"      \
      : "=r"((r)[0]), "=r"((r)[1]), "=r"((r)[2]), "=r"((r)[3]),              \
        "=r"((r)[4]), "=r"((r)[5]), "=r"((r)[6]), "=r"((r)[7]),              \
        "=r"((r)[8]), "=r"((r)[9]), "=r"((r)[10]), "=r"((r)[11]),            \
        "=r"((r)[12]), "=r"((r)[13]), "=r"((r)[14]), "=r"((r)[15])           \
      : "r"(a))
#endif  // HAS_TCGEN05

// ---------------------------------------------------------------------------
// Kernel 1: per-row precompute. grid 512, 256 thr, 2 i's/CTA; W1 staged in
// SMEM via cp.async so each CTA reads W1 once (no per-thread L2 storm).
//   T1[i,h] = x_i@(Wi+Wd) + b1   T2[i,h] = x_i@(Wj-Wd)   tau[i]
// ---------------------------------------------------------------------------
__global__ __launch_bounds__(THREADS) void precompute_kernel(
    const float* __restrict__ x, const float* __restrict__ W1,
    const float* __restrict__ b1, const float* __restrict__ Wt,
    const float* __restrict__ bt) {
  extern __shared__ __align__(16) char psmem[];
  float* Ws = (float*)(psmem + OFF_W);    // [192][128]
  float* xi = (float*)(psmem + OFF_PXI);  // [2][64]
  const uint32_t su = (uint32_t)__cvta_generic_to_shared(psmem);

  const int t = threadIdx.x;
  const int i0 = blockIdx.x * 2;
  const int io = t >> 7, h = t & 127;

  // stage W1 rows [0,192) : 6144 float4
#pragma unroll
  for (int r = 0; r < 24; r++) {
    const int e = t + r * THREADS;
    cp16(su + OFF_W + (uint32_t)e * 16, &W1[(size_t)e * 4]);
  }
  if (t < 2 * DD) xi[t] = x[(size_t)i0 * DD + t];
  asm volatile("cp.async.commit_group;" ::: "memory");
  asm volatile("cp.async.wait_group 0;" ::: "memory");
  __syncthreads();

  const float* xv = &xi[io * DD];
  float ai = 0.f, aj = 0.f, ad = 0.f;
#pragma unroll 8
  for (int d = 0; d < DD; ++d) {
    const float xd = xv[d];
    ai += xd * Ws[d * HH + h];
    aj += xd * Ws[(DD + d) * HH + h];
    ad += xd * Ws[(2 * DD + d) * HH + h];
  }
  g_T1[(size_t)(i0 + io) * HH + h] = ai + ad + b1[h];
  g_T2[(size_t)(i0 + io) * HH + h] = aj - ad;

  if (t < 2) {
    float z = bt[0];
#pragma unroll 8
    for (int d = 0; d < DD; ++d) z += xi[t * DD + d] * Wt[d];
    const float sp = (z > 20.f) ? z : log1pf(expf(z));
    g_tau[i0 + t] = fmaxf(sp, 0.01f) + 1.0f;
  }
}

// ---------------------------------------------------------------------------
// Kernel 2: tcgen05 pair-GEMM with T2 folded into the MMA:
//   D[h][j] = Wab^T @ |x_i - x_j|^T + (Wj-Wd)^T @ x_j^T
// CTA c: i0 = (c>>1)*2, jh = c&1 (4 j-tiles of 128). TMEM 256 cols ->
// 2 CTAs/SM. Epilogue: warp w -> h=(w&3)*32+lane, ch=w>>2; acc thread-local;
// each jh half writes its own g_Sp slab (no atomics).
// ---------------------------------------------------------------------------
__global__ __launch_bounds__(THREADS, 2)
void pair_kernel(const float* __restrict__ x, const float* __restrict__ W1) {
#if HAS_TCGEN05
  extern __shared__ __align__(16) char smem[];
  float* xi = (float*)(smem + OFF_XI);  // [2][64]
  float* Sc = (float*)(smem + OFF_SC);  // [2][2][128]
  const uint32_t su = (uint32_t)__cvta_generic_to_shared(smem);

  const int t = threadIdx.x;
  const int w = t >> 5, lane = t & 31;
  const int sub = w & 3, ch = w >> 2;
  const int h = sub * 32 + lane;
  const int ig = blockIdx.x >> 1, jh = blockIdx.x & 1;
  const int i0 = ig * IB;

  if (w == 0) {
    asm volatile(
        "tcgen05.alloc.cta_group::1.sync.aligned.shared::cta.b32 [%0], %1;"
        :: "r"(su + OFF_TPTR), "r"(256u)
        : "memory");
    asm volatile("tcgen05.relinquish_alloc_permit.cta_group::1.sync.aligned;");
  }
  if (t == 0) {
    asm volatile("mbarrier.init.shared.b64 [%0], %1;" ::"r"(su + OFF_MBAR),
                 "r"(1u)
                 : "memory");
  }
  __syncthreads();
  uint32_t tmem;
  asm volatile("ld.shared.b32 %0, [%1];" : "=r"(tmem) : "r"(su + OFF_TPTR));

  // A  = Wab^T:      A[m=h][k]  = W1[(192+k)*128 + m]
  // A2 = (Wj-Wd)^T:  A2[m=h][k] = W1[(64+k)*128+m] - W1[(128+k)*128+m]
#pragma unroll
  for (int r = 0; r < 16; r++) {
    const int e = t + r * THREADS;  // 4096 bf16x2
    const int m = e >> 5, kp = e & 31, k = kp * 2;
    const uint32_t so = sw128((uint32_t)(m * 128 + kp * 4));
    *(uint32_t*)(smem + OFF_A + so) = pack_bf2(
        W1[(size_t)(3 * DD + k) * HH + m], W1[(size_t)(3 * DD + k + 1) * HH + m]);
    *(uint32_t*)(smem + OFF_A2 + so) =
        pack_bf2(W1[(size_t)(DD + k) * HH + m] - W1[(size_t)(2 * DD + k) * HH + m],
                 W1[(size_t)(DD + k + 1) * HH + m] -
                     W1[(size_t)(2 * DD + k + 1) * HH + m]);
  }
  if (t < IB * DD) xi[t] = x[(size_t)i0 * DD + t];

  float t1v[IB], acc[IB];
#pragma unroll
  for (int ii = 0; ii < IB; ii++) {
    t1v[ii] = g_T1[(size_t)(i0 + ii) * HH + h];
    acc[ii] = 0.f;
  }
  __syncthreads();  // xi visible

  int ph = 0;
  const uint64_t adesc = smem_desc(su + OFF_A);
  const uint64_t a2desc = smem_desc(su + OFF_A2);
  const uint64_t bxdesc = smem_desc(su + OFF_BX);

  for (int tt = 0; tt < 4; tt++) {
    const int j0 = (jh * 4 + tt) * MT;

    // load x_j rows to regs (8 float4/thread), build BX + both |delta| tiles
    const int jr = t >> 4, kq = t & 15;  // row j = jr + r*16? no: e-based
#pragma unroll
    for (int r = 0; r < 8; r++) {
      const int e = t + r * THREADS;
      const int j = e >> 4, kp = e & 15, k = kp * 4;
      const float4 xj4 = *(const float4*)&x[(size_t)(j0 + j) * DD + k];
      const uint32_t so = sw128((uint32_t)(j * 128 + kp * 8));
      uint2 bx;
      bx.x = pack_bf2(xj4.x, xj4.y);
      bx.y = pack_bf2(xj4.z, xj4.w);
      *(uint2*)(smem + OFF_BX + so) = bx;
#pragma unroll
      for (int ii = 0; ii < IB; ii++) {
        const float* xiv = &xi[ii * DD];
        uint2 o;
        o.x = pack_bf2(fabsf(xj4.x - xiv[k]), fabsf(xj4.y - xiv[k + 1]));
        o.y = pack_bf2(fabsf(xj4.z - xiv[k + 2]), fabsf(xj4.w - xiv[k + 3]));
        *(uint2*)(smem + OFF_B + ii * 16384 + so) = o;
      }
    }
    asm volatile("fence.proxy.async.shared::cta;" ::: "memory");
    __syncthreads();

    if (t == 0) {
#pragma unroll
      for (int ii = 0; ii < IB; ii++) {
        const uint64_t bdesc = smem_desc(su + OFF_B + ii * 16384);
#pragma unroll
        for (int ks = 0; ks < 4; ks++)
          mma_f16_ss(tmem + ii * 128, adesc + ks * 2, bdesc + ks * 2, IDESC,
                     ks > 0);
#pragma unroll
        for (int ks = 0; ks < 4; ks++)
          mma_f16_ss(tmem + ii * 128, a2desc + ks * 2, bxdesc + ks * 2, IDESC,
                     true);
      }
      asm volatile(
          "tcgen05.commit.cta_group::1.mbarrier::arrive::one.shared::cluster."
          "b64 [%0];" ::"r"(su + OFF_MBAR)
          : "memory");
    }
    mbar_wait(su + OFF_MBAR, ph);
    ph ^= 1;
    asm volatile("tcgen05.fence::after_thread_sync;" ::: "memory");

    // Epilogue: pure LDTM + relu-sum (no T2 anymore)
#pragma unroll
    for (int c = 0; c < 4; c++) {
#pragma unroll
      for (int ii = 0; ii < IB; ii++) {
        uint32_t Dr[16];
        LDTM_X16(Dr, tmem + ii * 128 + c * 32 + ch * 16);
        asm volatile("tcgen05.wait::ld.sync.aligned;" ::: "memory");
        float a = 0.f;
#pragma unroll
        for (int r = 0; r < 16; r++)
          a += fmaxf(__uint_as_float(Dr[r]) + t1v[ii], 0.f);
        acc[ii] += a;
      }
    }
    asm volatile("tcgen05.fence::before_thread_sync;" ::: "memory");
    __syncthreads();  // LDTM done before next tile's MMAs / smem rebuild
  }

  // Combine col-halves; one writer per (jh,i,h) -> plain store
#pragma unroll
  for (int ii = 0; ii < IB; ii++) Sc[(ii * 2 + ch) * 128 + h] = acc[ii];
  __syncthreads();
  if (t < HH) {
#pragma unroll
    for (int ii = 0; ii < IB; ii++)
      g_Sp[jh][(size_t)(i0 + ii) * HH + t] =
          Sc[(ii * 2 + 0) * 128 + t] + Sc[(ii * 2 + 1) * 128 + t];
  }
  __syncthreads();
  if (t == 0)
    asm volatile("mbarrier.inval.shared.b64 [%0];" ::"r"(su + OFF_MBAR)
                 : "memory");
  __syncthreads();
  if (w == 0)
    asm volatile("tcgen05.dealloc.cta_group::1.sync.aligned.b32 %0, %1;" ::"r"(
                     tmem),
                 "r"(256u));
#else
  // Fallback for the generic compute_103 PTX pass (correctness-only; the
  // sm_103a cubin is what runs on GB300).
  const int t = threadIdx.x;
  const int h = t & 127;
  const int io = t >> 7;
  const int ig = blockIdx.x >> 1, jh = blockIdx.x & 1;
  const int i = ig * IB + io;
  float wcol[DD];
  for (int d = 0; d < DD; d++) wcol[d] = W1[(size_t)(3 * DD + d) * HH + h];
  const float t1 = g_T1[(size_t)i * HH + h];
  float s = 0.f;
  for (int j = jh * 512; j < jh * 512 + 512; j++) {
    float ta = 0.f;
    for (int d = 0; d < DD; d++)
      ta += fabsf(x[(size_t)i * DD + d] - x[(size_t)j * DD + d]) * wcol[d];
    s += fmaxf(ta + t1 + g_T2[(size_t)j * HH + h], 0.f);
  }
  g_Sp[jh][(size_t)i * HH + h] = s;
#endif
}

// ---------------------------------------------------------------------------
// Kernel 3: head + layernorm per row
// ---------------------------------------------------------------------------
__global__ __launch_bounds__(HH) void head_kernel(
    const float* __restrict__ x, const float* __restrict__ W2,
    const float* __restrict__ b2, const float* __restrict__ Wa,
    const float* __restrict__ ba, const float* __restrict__ Wr,
    const float* __restrict__ br, const float* __restrict__ gamma,
    const float* __restrict__ beta, float* __restrict__ out) {
  __shared__ float S_s[HH], hm_s[HH], xi[DD];
  __shared__ float red[4];
  const int i = blockIdx.x;
  const int t = threadIdx.x;
  const int w = t >> 5, lane = t & 31;

  if (t < DD) xi[t] = x[i * DD + t];
  S_s[t] = (g_Sp[0][(size_t)i * HH + t] + g_Sp[1][(size_t)i * HH + t]) *
           (1.0f / BB);
  __syncthreads();

  float acc = b2[t];
#pragma unroll 8
  for (int k = 0; k < HH; ++k) acc += S_s[k] * W2[k * HH + t];
  hm_s[t] = acc / g_tau[i];
  __syncthreads();

  float acc2 = ba[t];
#pragma unroll 8
  for (int k = 0; k < HH; ++k) acc2 += hm_s[k] * Wa[k * HH + t];
  const float hv = fmaxf(acc2, 0.f);
  float a3 = br[t];
#pragma unroll 8
  for (int d = 0; d < DD; ++d) a3 += xi[d] * Wr[d * HH + t];
  const float yv = hv + a3;

  float v = yv;
#pragma unroll
  for (int off = 16; off > 0; off >>= 1) v += __shfl_xor_sync(0xffffffffu, v, off);
  if (lane == 0) red[w] = v;
  __syncthreads();
  const float mu = (red[0] + red[1] + red[2] + red[3]) * (1.0f / HH);
  __syncthreads();
  const float dv = yv - mu;
  float v2 = dv * dv;
#pragma unroll
  for (int off = 16; off > 0; off >>= 1) v2 += __shfl_xor_sync(0xffffffffu, v2, off);
  if (lane == 0) red[w] = v2;
  __syncthreads();
  const float var = (red[0] + red[1] + red[2] + red[3]) * (1.0f / HH);

  out[(size_t)i * HH + t] = dv * rsqrtf(var + 1e-5f) * gamma[t] + beta[t];
}

// ---------------------------------------------------------------------------
// Inputs: 0:x 1:W1 2:b1 3:W2 4:b2 5:Wt 6:bt 7:Wa 8:ba 9:Wr 10:br 11:gamma 12:beta
// ---------------------------------------------------------------------------
extern "C" void kernel_launch(void* const* d_in, const int* in_sizes, int n_in,
                              void* d_out, int out_size) {
  const float* x     = (const float*)d_in[0];
  const float* W1    = (const float*)d_in[1];
  const float* b1    = (const float*)d_in[2];
  const float* W2    = (const float*)d_in[3];
  const float* b2    = (const float*)d_in[4];
  const float* Wt    = (const float*)d_in[5];
  const float* bt    = (const float*)d_in[6];
  const float* Wa    = (const float*)d_in[7];
  const float* ba    = (const float*)d_in[8];
  const float* Wr    = (const float*)d_in[9];
  const float* br    = (const float*)d_in[10];
  const float* gamma = (const float*)d_in[11];
  const float* beta  = (const float*)d_in[12];
  float* out = (float*)d_out;

  cudaFuncSetAttribute(precompute_kernel,
                       cudaFuncAttributeMaxDynamicSharedMemorySize, PRE_SMEM);
  cudaFuncSetAttribute(pair_kernel, cudaFuncAttributeMaxDynamicSharedMemorySize,
                       SMEM_TOTAL);
  precompute_kernel<<<BB / 2, THREADS, PRE_SMEM>>>(x, W1, b1, Wt, bt);
  pair_kernel<<<BB / IB * 2, THREADS, SMEM_TOTAL>>>(x, W1);
  head_kernel<<<BB, HH>>>(x, W2, b2, Wa, ba, Wr, br, gamma, beta, out);
}

// round 9
// speedup vs baseline: 2.2771x; 2.2771x over previous
#include <cuda_runtime.h>
#include <cuda_bf16.h>
#include <math.h>
#include <stdint.h>

#define BB 1024
#define DD 64
#define HH 128
#define IB 2            // i's per CTA
#define NT 8            // j-tiles (128 each) per CTA
#define THREADS 256

#if defined(__CUDA_ARCH_FEAT_SM103_ALL) || defined(__CUDA_ARCH_FEAT_SM100_ALL) || \
    defined(__CUDA_ARCH_FEAT_SM101_ALL)
#define HAS_TCGEN05 1
#else
#define HAS_TCGEN05 0
#endif

// pair kernel dynamic smem layout (bytes)
#define OFF_A     0          // Wab^T bf16 image, 16384
#define OFF_A2    16384      // (Wj-Wd)^T bf16 image, 16384
#define OFF_BX    32768      // 2 x bf16 x_j tile image, 32768
#define OFF_B     65536      // 2 x |delta| bf16 [128j x 64k] SW128, 32768
#define OFF_SC    98304      // S partials f32 [2][2][128], 2048
#define OFF_MBAR  100352
#define OFF_TPTR  100360
#define SMEM_TOTAL 100384

// precompute kernel smem
#define OFF_W     0          // W1 rows 0..191 f32, 98304
#define OFF_PXI   98304      // x_i f32 [2 x 64], 512
#define PRE_SMEM  98816

// idesc: dtype=F32, a=BF16, b=BF16, N=128, M=128 (proven R7/R8)
#define IDESC ((1u << 4) | (1u << 7) | (1u << 10) | ((HH / 8) << 17) | (8u << 24))

// Scratch
__device__ __align__(16) float g_T1[BB * HH];
__device__ __align__(16) float g_T2[BB * HH];   // fallback path only
__device__ __align__(16) float g_S[BB * HH];
__device__ float g_tau[BB];
// bf16 SW128 SMEM-images, built once by precompute_kernel
__device__ __align__(16) uint32_t g_Aimg[4096];    // 16KB
__device__ __align__(16) uint32_t g_A2img[4096];   // 16KB
__device__ __align__(16) uint32_t g_Ximg[32768];   // 8 tile-images x 16KB

__device__ __forceinline__ uint32_t pack_bf2(float lo, float hi) {
  __nv_bfloat162 v = __floats2bfloat162_rn(lo, hi);
  return *(uint32_t*)&v;
}
__device__ __forceinline__ uint32_t habs_sub2(uint32_t a, uint32_t b) {
  __nv_bfloat162 av = *(__nv_bfloat162*)&a, bv = *(__nv_bfloat162*)&b;
  __nv_bfloat162 r = __habs2(__hsub2(av, bv));
  return *(uint32_t*)&r;
}
__device__ __host__ __forceinline__ uint32_t sw128(uint32_t o) {
  return o ^ ((o >> 3) & 0x70);
}
__device__ __forceinline__ uint64_t smem_desc(uint32_t addr) {
  return (2ull << 61) | (1ull << 46) | (64ull << 32) | (1ull << 16) |
         ((uint64_t)(addr >> 4) & 0x3FFF);
}
__device__ __forceinline__ void cp16(uint32_t smem_dst, const void* gsrc) {
  asm volatile("cp.async.cg.shared.global [%0], [%1], 16;" ::"r"(smem_dst),
               "l"(gsrc)
               : "memory");
}

#if HAS_TCGEN05
__device__ __forceinline__ void mma_f16_ss(uint32_t d, uint64_t ad, uint64_t bd,
                                           uint32_t idesc, bool accum) {
  uint32_t en = accum ? 1u : 0u;
  asm volatile(
      "{\n\t.reg .pred p;\n\tsetp.ne.u32 p, %5, 0;\n\t"
      "tcgen05.mma.cta_group::1.kind::f16 [%0], %1, %2, %3, {%4,%4,%4,%4}, "
      "p;\n\t}"
      :: "r"(d), "l"(ad), "l"(bd), "r"(idesc), "r"(0u), "r"(en)
      : "memory");
}
__device__ __forceinline__ void mbar_wait(uint32_t mbar, int parity) {
  asm volatile(
      "{\n\t.reg .pred P;\n\t"
      "WL%=:\n\t"
      "mbarrier.try_wait.parity.acquire.cta.shared::cta.b64 P, [%0], %1, "
      "0x989680;\n\t"
      "@P bra WD%=;\n\t"
      "bra WL%=;\n\t"
      "WD%=:\n\t}"
      :: "r"(mbar), "r"((uint32_t)parity)
      : "memory");
}
#define LDTM_X16(r, a)                                                       \
  asm volatile(                                                              \
      "tcgen05.ld.sync.aligned.32x32b.x16.b32 "                              \
      "{%0,%1,%2,%3,%4,%5,%6,%7,%8,%9,%10,%11,%12,%13,%14,%15}, [%16];"      \
      : "=r"((r)[0]), "=r"((r)[1]), "=r"((r)[2]), "=r"((r)[3]),              \
        "=r"((r)[4]), "=r"((r)[5]), "=r"((r)[6]), "=r"((r)[7]),              \
        "=r"((r)[8]), "=r"((r)[9]), "=r"((r)[10]), "=r"((r)[11]),            \
        "=r"((r)[12]), "=r"((r)[13]), "=r"((r)[14]), "=r"((r)[15])           \
      : "r"(a))
#endif  // HAS_TCGEN05

// ---------------------------------------------------------------------------
// Kernel 1: per-row precompute (W1 staged in smem), plus one-time bf16
// SW128 image builds (blocks 0..39 only): g_Ximg, g_Aimg, g_A2img.
// ---------------------------------------------------------------------------
__global__ __launch_bounds__(THREADS) void precompute_kernel(
    const float* __restrict__ x, const float* __restrict__ W1,
    const float* __restrict__ b1, const float* __restrict__ Wt,
    const float* __restrict__ bt) {
  extern __shared__ __align__(16) char psmem[];
  float* Ws = (float*)(psmem + OFF_W);
  float* xi = (float*)(psmem + OFF_PXI);
  const uint32_t su = (uint32_t)__cvta_generic_to_shared(psmem);

  const int t = threadIdx.x;
  const int b = blockIdx.x;
  const int i0 = b * 2;
  const int io = t >> 7, h = t & 127;

#pragma unroll
  for (int r = 0; r < 24; r++) {
    const int e = t + r * THREADS;
    cp16(su + OFF_W + (uint32_t)e * 16, &W1[(size_t)e * 4]);
  }
  if (t < 2 * DD) xi[t] = x[(size_t)i0 * DD + t];
  asm volatile("cp.async.commit_group;" ::: "memory");

  // -------- image building (runs while W1 staging is in flight) --------
  if (b < 32) {  // g_Ximg: x -> bf16, 8 SW128 tile images of [128 x 64]
#pragma unroll
    for (int q = 0; q < 2; q++) {
      const int e = b * 512 + t + q * THREADS;  // uint2 idx = j*16 + kp
      const int j = e >> 4, kp = e & 15, k = kp * 4;
      const float4 x4 = *(const float4*)&x[(size_t)j * DD + k];
      uint2 o;
      o.x = pack_bf2(x4.x, x4.y);
      o.y = pack_bf2(x4.z, x4.w);
      const int tile = j >> 7, jl = j & 127;
      *(uint2*)((char*)g_Ximg + tile * 16384 + sw128(jl * 128 + kp * 8)) = o;
    }
  } else if (b < 36) {  // g_Aimg: Wab^T
#pragma unroll
    for (int q = 0; q < 2; q++) {
      const int e = (b - 32) * 512 + t + q * THREADS;  // m*16 + kp
      const int m = e >> 4, kp = e & 15, k = kp * 4;
      uint2 o;
      o.x = pack_bf2(W1[(size_t)(3 * DD + k) * HH + m],
                     W1[(size_t)(3 * DD + k + 1) * HH + m]);
      o.y = pack_bf2(W1[(size_t)(3 * DD + k + 2) * HH + m],
                     W1[(size_t)(3 * DD + k + 3) * HH + m]);
      *(uint2*)((char*)g_Aimg + sw128(m * 128 + kp * 8)) = o;
    }
  } else if (b < 40) {  // g_A2img: (Wj - Wd)^T
#pragma unroll
    for (int q = 0; q < 2; q++) {
      const int e = (b - 36) * 512 + t + q * THREADS;
      const int m = e >> 4, kp = e & 15, k = kp * 4;
      uint2 o;
      o.x = pack_bf2(
          W1[(size_t)(DD + k) * HH + m] - W1[(size_t)(2 * DD + k) * HH + m],
          W1[(size_t)(DD + k + 1) * HH + m] -
              W1[(size_t)(2 * DD + k + 1) * HH + m]);
      o.y = pack_bf2(
          W1[(size_t)(DD + k + 2) * HH + m] -
              W1[(size_t)(2 * DD + k + 2) * HH + m],
          W1[(size_t)(DD + k + 3) * HH + m] -
              W1[(size_t)(2 * DD + k + 3) * HH + m]);
      *(uint2*)((char*)g_A2img + sw128(m * 128 + kp * 8)) = o;
    }
  }

  asm volatile("cp.async.wait_group 0;" ::: "memory");
  __syncthreads();

  const float* xv = &xi[io * DD];
  float ai = 0.f, aj = 0.f, ad = 0.f;
#pragma unroll 8
  for (int d = 0; d < DD; ++d) {
    const float xd = xv[d];
    ai += xd * Ws[d * HH + h];
    aj += xd * Ws[(DD + d) * HH + h];
    ad += xd * Ws[(2 * DD + d) * HH + h];
  }
  g_T1[(size_t)(i0 + io) * HH + h] = ai + ad + b1[h];
  g_T2[(size_t)(i0 + io) * HH + h] = aj - ad;

  if (t < 2) {
    float z = bt[0];
#pragma unroll 8
    for (int d = 0; d < DD; ++d) z += xi[t * DD + d] * Wt[d];
    const float sp = (z > 20.f) ? z : log1pf(expf(z));
    g_tau[i0 + t] = fmaxf(sp, 0.01f) + 1.0f;
  }
}

// ---------------------------------------------------------------------------
// Kernel 2: tcgen05 pair-GEMM, T2 folded:
//   D[h][j] = Wab^T @ |x_i - x_j|^T + (Wj-Wd)^T @ x_j^T
// grid 512 (one CTA per i-pair, all 8 j-tiles). TMEM 256 cols, 2 CTAs/SM.
// All operands staged from precomputed bf16 images; |delta| built in bf16
// from smem BX (double-buffered cp.async) + 2 regs of x_i. Plain g_S store.
// ---------------------------------------------------------------------------
__global__ __launch_bounds__(THREADS, 2)
void pair_kernel(const float* __restrict__ x, const float* __restrict__ W1) {
#if HAS_TCGEN05
  extern __shared__ __align__(16) char smem[];
  float* Sc = (float*)(smem + OFF_SC);  // [2][2][128]
  const uint32_t su = (uint32_t)__cvta_generic_to_shared(smem);

  const int t = threadIdx.x;
  const int w = t >> 5, lane = t & 31;
  const int sub = w & 3, ch = w >> 2;
  const int h = sub * 32 + lane;
  const int i0 = blockIdx.x * IB;
  const int kp = t & 15;

  if (w == 0) {
    asm volatile(
        "tcgen05.alloc.cta_group::1.sync.aligned.shared::cta.b32 [%0], %1;"
        :: "r"(su + OFF_TPTR), "r"(256u)
        : "memory");
    asm volatile("tcgen05.relinquish_alloc_permit.cta_group::1.sync.aligned;");
  }
  if (t == 0) {
    asm volatile("mbarrier.init.shared.b64 [%0], %1;" ::"r"(su + OFF_MBAR),
                 "r"(1u)
                 : "memory");
  }

  // stage A, A2 images + BX tile 0 (all contiguous, coalesced)
#pragma unroll
  for (int r = 0; r < 4; r++) {
    const int e = t + r * THREADS;  // 1024 x 16B each
    cp16(su + OFF_A + (uint32_t)e * 16, (const char*)g_Aimg + e * 16);
    cp16(su + OFF_A2 + (uint32_t)e * 16, (const char*)g_A2img + e * 16);
    cp16(su + OFF_BX + (uint32_t)e * 16, (const char*)g_Ximg + e * 16);
  }
  asm volatile("cp.async.commit_group;" ::: "memory");

  // x_i bf16 (this thread's kp slice) + T1 columns
  uint2 xib[IB];
  float t1v[IB], acc[IB];
#pragma unroll
  for (int ii = 0; ii < IB; ii++) {
    const int gi = i0 + ii;
    xib[ii] = *(const uint2*)((const char*)g_Ximg + (gi >> 7) * 16384 +
                              sw128((uint32_t)((gi & 127) * 128 + kp * 8)));
    t1v[ii] = g_T1[(size_t)gi * HH + h];
    acc[ii] = 0.f;
  }
  __syncthreads();
  uint32_t tmem;
  asm volatile("ld.shared.b32 %0, [%1];" : "=r"(tmem) : "r"(su + OFF_TPTR));

  int ph = 0;
  const uint64_t adesc = smem_desc(su + OFF_A);
  const uint64_t a2desc = smem_desc(su + OFF_A2);

  for (int tt = 0; tt < NT; tt++) {
    const int cur = tt & 1;
    // prefetch next BX tile into the other buffer
    if (tt + 1 < NT) {
#pragma unroll
      for (int r = 0; r < 4; r++) {
        const int e = t + r * THREADS;
        cp16(su + OFF_BX + (uint32_t)((cur ^ 1) * 16384 + e * 16),
             (const char*)g_Ximg + (tt + 1) * 16384 + e * 16);
      }
    }
    asm volatile("cp.async.commit_group;" ::: "memory");
    asm volatile("cp.async.wait_group 1;" ::: "memory");  // BX(tt) ready
    __syncthreads();

    // build |delta| tiles in bf16, all from smem
#pragma unroll
    for (int r = 0; r < 8; r++) {
      const int e = t + r * THREADS;
      const int j = e >> 4;  // kp fixed = t & 15
      const uint32_t so = sw128((uint32_t)(j * 128 + kp * 8));
      const uint2 bx = *(const uint2*)(smem + OFF_BX + cur * 16384 + so);
#pragma unroll
      for (int ii = 0; ii < IB; ii++) {
        uint2 o;
        o.x = habs_sub2(bx.x, xib[ii].x);
        o.y = habs_sub2(bx.y, xib[ii].y);
        *(uint2*)(smem + OFF_B + ii * 16384 + so) = o;
      }
    }
    asm volatile("fence.proxy.async.shared::cta;" ::: "memory");
    __syncthreads();

    if (t == 0) {
      const uint64_t bxdesc = smem_desc(su + OFF_BX + cur * 16384);
#pragma unroll
      for (int ii = 0; ii < IB; ii++) {
        const uint64_t bdesc = smem_desc(su + OFF_B + ii * 16384);
#pragma unroll
        for (int ks = 0; ks < 4; ks++)
          mma_f16_ss(tmem + ii * 128, adesc + ks * 2, bdesc + ks * 2, IDESC,
                     ks > 0);
#pragma unroll
        for (int ks = 0; ks < 4; ks++)
          mma_f16_ss(tmem + ii * 128, a2desc + ks * 2, bxdesc + ks * 2, IDESC,
                     true);
      }
      asm volatile(
          "tcgen05.commit.cta_group::1.mbarrier::arrive::one.shared::cluster."
          "b64 [%0];" ::"r"(su + OFF_MBAR)
          : "memory");
    }
    mbar_wait(su + OFF_MBAR, ph);
    ph ^= 1;
    asm volatile("tcgen05.fence::after_thread_sync;" ::: "memory");

    // epilogue: pure LDTM + relu-sum, thread-local over j
#pragma unroll
    for (int c = 0; c < 4; c++) {
#pragma unroll
      for (int ii = 0; ii < IB; ii++) {
        uint32_t Dr[16];
        LDTM_X16(Dr, tmem + ii * 128 + c * 32 + ch * 16);
        asm volatile("tcgen05.wait::ld.sync.aligned;" ::: "memory");
        float a = 0.f;
#pragma unroll
        for (int r = 0; r < 16; r++)
          a += fmaxf(__uint_as_float(Dr[r]) + t1v[ii], 0.f);
        acc[ii] += a;
      }
    }
    asm volatile("tcgen05.fence::before_thread_sync;" ::: "memory");
    __syncthreads();  // LDTM + BX reads done before next build/MMA
  }

  // combine col-halves; single writer per (i,h) -> plain store
#pragma unroll
  for (int ii = 0; ii < IB; ii++) Sc[(ii * 2 + ch) * 128 + h] = acc[ii];
  __syncthreads();
  if (t < HH) {
#pragma unroll
    for (int ii = 0; ii < IB; ii++)
      g_S[(size_t)(i0 + ii) * HH + t] =
          Sc[(ii * 2 + 0) * 128 + t] + Sc[(ii * 2 + 1) * 128 + t];
  }
  __syncthreads();
  if (t == 0)
    asm volatile("mbarrier.inval.shared.b64 [%0];" ::"r"(su + OFF_MBAR)
                 : "memory");
  __syncthreads();
  if (w == 0)
    asm volatile("tcgen05.dealloc.cta_group::1.sync.aligned.b32 %0, %1;" ::"r"(
                     tmem),
                 "r"(256u));
#else
  // Fallback for the generic compute_103 PTX pass (correctness-only).
  const int t = threadIdx.x;
  const int h = t & 127;
  const int io = t >> 7;
  const int i = blockIdx.x * IB + io;
  float wcol[DD];
  for (int d = 0; d < DD; d++) wcol[d] = W1[(size_t)(3 * DD + d) * HH + h];
  const float t1 = g_T1[(size_t)i * HH + h];
  float s = 0.f;
  for (int j = 0; j < BB; j++) {
    float ta = 0.f;
    for (int d = 0; d < DD; d++)
      ta += fabsf(x[(size_t)i * DD + d] - x[(size_t)j * DD + d]) * wcol[d];
    s += fmaxf(ta + t1 + g_T2[(size_t)j * HH + h], 0.f);
  }
  g_S[(size_t)i * HH + h] = s;
#endif
}

// ---------------------------------------------------------------------------
// Kernel 3: head + layernorm per row
// ---------------------------------------------------------------------------
__global__ __launch_bounds__(HH) void head_kernel(
    const float* __restrict__ x, const float* __restrict__ W2,
    const float* __restrict__ b2, const float* __restrict__ Wa,
    const float* __restrict__ ba, const float* __restrict__ Wr,
    const float* __restrict__ br, const float* __restrict__ gamma,
    const float* __restrict__ beta, float* __restrict__ out) {
  __shared__ float S_s[HH], hm_s[HH], xi[DD];
  __shared__ float red[4];
  const int i = blockIdx.x;
  const int t = threadIdx.x;
  const int w = t >> 5, lane = t & 31;

  if (t < DD) xi[t] = x[i * DD + t];
  S_s[t] = g_S[(size_t)i * HH + t] * (1.0f / BB);
  __syncthreads();

  float acc = b2[t];
#pragma unroll 8
  for (int k = 0; k < HH; ++k) acc += S_s[k] * W2[k * HH + t];
  hm_s[t] = acc / g_tau[i];
  __syncthreads();

  float acc2 = ba[t];
#pragma unroll 8
  for (int k = 0; k < HH; ++k) acc2 += hm_s[k] * Wa[k * HH + t];
  const float hv = fmaxf(acc2, 0.f);
  float a3 = br[t];
#pragma unroll 8
  for (int d = 0; d < DD; ++d) a3 += xi[d] * Wr[d * HH + t];
  const float yv = hv + a3;

  float v = yv;
#pragma unroll
  for (int off = 16; off > 0; off >>= 1) v += __shfl_xor_sync(0xffffffffu, v, off);
  if (lane == 0) red[w] = v;
  __syncthreads();
  const float mu = (red[0] + red[1] + red[2] + red[3]) * (1.0f / HH);
  __syncthreads();
  const float dv = yv - mu;
  float v2 = dv * dv;
#pragma unroll
  for (int off = 16; off > 0; off >>= 1) v2 += __shfl_xor_sync(0xffffffffu, v2, off);
  if (lane == 0) red[w] = v2;
  __syncthreads();
  const float var = (red[0] + red[1] + red[2] + red[3]) * (1.0f / HH);

  out[(size_t)i * HH + t] = dv * rsqrtf(var + 1e-5f) * gamma[t] + beta[t];
}

// ---------------------------------------------------------------------------
// Inputs: 0:x 1:W1 2:b1 3:W2 4:b2 5:Wt 6:bt 7:Wa 8:ba 9:Wr 10:br 11:gamma 12:beta
// ---------------------------------------------------------------------------
extern "C" void kernel_launch(void* const* d_in, const int* in_sizes, int n_in,
                              void* d_out, int out_size) {
  const float* x     = (const float*)d_in[0];
  const float* W1    = (const float*)d_in[1];
  const float* b1    = (const float*)d_in[2];
  const float* W2    = (const float*)d_in[3];
  const float* b2    = (const float*)d_in[4];
  const float* Wt    = (const float*)d_in[5];
  const float* bt    = (const float*)d_in[6];
  const float* Wa    = (const float*)d_in[7];
  const float* ba    = (const float*)d_in[8];
  const float* Wr    = (const float*)d_in[9];
  const float* br    = (const float*)d_in[10];
  const float* gamma = (const float*)d_in[11];
  const float* beta  = (const float*)d_in[12];
  float* out = (float*)d_out;

  cudaFuncSetAttribute(precompute_kernel,
                       cudaFuncAttributeMaxDynamicSharedMemorySize, PRE_SMEM);
  cudaFuncSetAttribute(pair_kernel, cudaFuncAttributeMaxDynamicSharedMemorySize,
                       SMEM_TOTAL);
  precompute_kernel<<<BB / 2, THREADS, PRE_SMEM>>>(x, W1, b1, Wt, bt);
  pair_kernel<<<BB / IB, THREADS, SMEM_TOTAL>>>(x, W1);
  head_kernel<<<BB, HH>>>(x, W2, b2, Wa, ba, Wr, br, gamma, beta, out);
}